// round 1
// baseline (speedup 1.0000x reference)
#include <cuda_runtime.h>
#include <cuda_bf16.h>

#define NN   8192
#define FIN  256
#define FOUT 128

// ---------------- device scratch (no allocations allowed) ----------------
__device__ float g_Wh[NN * FOUT];   // 4 MB
__device__ float g_s1[NN];
__device__ float g_s2[NN];

// ---------------- Kernel 1: Wh = h @ W, s1 = Wh@a1, s2 = Wh@a2 ----------------
// grid 128 blocks x 256 threads; block computes 64 rows x 128 cols.
__global__ __launch_bounds__(256) void k1_gemm_s(
    const float* __restrict__ h, const float* __restrict__ W,
    const float* __restrict__ a)
{
    __shared__ float h_t[64][36];     // 64 x 32 K-tile, pad 36 (bank-safe, 16B aligned)
    __shared__ float W_t[32][FOUT];   // 32 x 128

    const int t  = threadIdx.x;
    const int tx = t & 15;            // col group: ff0 = tx*8
    const int ty = t >> 4;            // row group: ii0 = ty*4
    const int row0 = blockIdx.x * 64;

    float acc[4][8];
#pragma unroll
    for (int r = 0; r < 4; r++)
#pragma unroll
        for (int c = 0; c < 8; c++) acc[r][c] = 0.0f;

    for (int k0 = 0; k0 < FIN; k0 += 32) {
        // load h tile: 64 rows x 8 float4
        for (int l = t; l < 64 * 8; l += 256) {
            int r = l >> 3, c4 = l & 7;
            float4 v = *(const float4*)&h[(size_t)(row0 + r) * FIN + k0 + c4 * 4];
            *(float4*)&h_t[r][c4 * 4] = v;
        }
        // load W tile: 32 rows x 32 float4
        for (int l = t; l < 32 * 32; l += 256) {
            int r = l >> 5, c4 = l & 31;
            *(float4*)&W_t[r][c4 * 4] = *(const float4*)&W[(size_t)(k0 + r) * FOUT + c4 * 4];
        }
        __syncthreads();

#pragma unroll 8
        for (int k = 0; k < 32; k++) {
            float bf[8];
            *(float4*)&bf[0] = *(const float4*)&W_t[k][tx * 8];
            *(float4*)&bf[4] = *(const float4*)&W_t[k][tx * 8 + 4];
            float af[4];
#pragma unroll
            for (int r = 0; r < 4; r++) af[r] = h_t[ty * 4 + r][k];
#pragma unroll
            for (int r = 0; r < 4; r++)
#pragma unroll
                for (int c = 0; c < 8; c++)
                    acc[r][c] = fmaf(af[r], bf[c], acc[r][c]);
        }
        __syncthreads();
    }

    // a1/a2 fragments for this thread's 8 columns
    float a1f[8], a2f[8];
#pragma unroll
    for (int c = 0; c < 8; c++) {
        a1f[c] = a[tx * 8 + c];
        a2f[c] = a[FOUT + tx * 8 + c];
    }

#pragma unroll
    for (int r = 0; r < 4; r++) {
        int row = row0 + ty * 4 + r;
        // write Wh
        float4 v0 = make_float4(acc[r][0], acc[r][1], acc[r][2], acc[r][3]);
        float4 v1 = make_float4(acc[r][4], acc[r][5], acc[r][6], acc[r][7]);
        *(float4*)&g_Wh[(size_t)row * FOUT + tx * 8]     = v0;
        *(float4*)&g_Wh[(size_t)row * FOUT + tx * 8 + 4] = v1;
        // partial dots for s1/s2
        float p1 = 0.f, p2 = 0.f;
#pragma unroll
        for (int c = 0; c < 8; c++) {
            p1 = fmaf(acc[r][c], a1f[c], p1);
            p2 = fmaf(acc[r][c], a2f[c], p2);
        }
        // reduce across the 16 tx threads (contiguous 16-lane half groups)
#pragma unroll
        for (int o = 8; o >= 1; o >>= 1) {
            p1 += __shfl_xor_sync(0xffffffffu, p1, o);
            p2 += __shfl_xor_sync(0xffffffffu, p2, o);
        }
        if (tx == 0) {
            g_s1[row] = p1;
            g_s2[row] = p2;
        }
    }
}

// ---------------- Kernel 2: fused masked-exp attention @ Wh ----------------
// grid 128 blocks (BI=64 rows each) x 256 threads; streams 64 j-tiles of BJ=128.
// Dynamic smem layout (floats):
//   Wh_s : 128*128          (j-tile of Wh)
//   P_s  : 64*132           (P[ii][jj], padded row 132)
//   s2_s : 128
//   s1_s : 64
//   den_s: 64
#define K2_SMEM_FLOATS (128 * 128 + 64 * 132 + 128 + 64 + 64)
#define K2_SMEM_BYTES  (K2_SMEM_FLOATS * 4)

__global__ __launch_bounds__(256) void k2_attn(
    const int* __restrict__ adj, float* __restrict__ out)
{
    extern __shared__ float smem[];
    float* Wh_s  = smem;                       // [128][128]
    float* P_s   = Wh_s + 128 * 128;           // [64][132]
    float* s2_s  = P_s + 64 * 132;             // [128]
    float* s1_s  = s2_s + 128;                 // [64]
    float* den_s = s1_s + 64;                  // [64]

    const int t    = threadIdx.x;
    const int lane = t & 31;
    const int w    = t >> 5;                   // warp id 0..7
    const int tx   = t & 15;                   // ff0 = tx*8
    const int ty   = t >> 4;                   // ii0 = ty*4
    const int i0   = blockIdx.x * 64;

    if (t < 64) {
        s1_s[t]  = g_s1[i0 + t];
        den_s[t] = 0.0f;
    }

    float acc[4][8];
#pragma unroll
    for (int r = 0; r < 4; r++)
#pragma unroll
        for (int c = 0; c < 8; c++) acc[r][c] = 0.0f;

    for (int j0 = 0; j0 < NN; j0 += 128) {
        // ---- load Wh j-tile (128 x 128) and s2 ----
        for (int l = t; l < 128 * 32; l += 256) {
            int r = l >> 5, c4 = l & 31;
            *(float4*)&Wh_s[r * 128 + c4 * 4] =
                *(const float4*)&g_Wh[(size_t)(j0 + r) * FOUT + c4 * 4];
        }
        if (t < 128) s2_s[t] = g_s2[j0 + t];
        __syncthreads();

        // ---- phase 1: P tile (64 x 128), masked exp, row sums ----
        {
            // prefetch the 8 adj rows this warp owns (MLP=8)
            int4 av[8];
#pragma unroll
            for (int r = 0; r < 8; r++) {
                int ii = w * 8 + r;
                av[r] = *(const int4*)&adj[(size_t)(i0 + ii) * NN + j0 + lane * 4];
            }
#pragma unroll
            for (int r = 0; r < 8; r++) {
                int ii = w * 8 + r;
                float s1v = s1_s[ii];
                float e0 = s1v + s2_s[lane * 4 + 0];
                float e1 = s1v + s2_s[lane * 4 + 1];
                float e2 = s1v + s2_s[lane * 4 + 2];
                float e3 = s1v + s2_s[lane * 4 + 3];
                // leaky_relu(x, 0.2) == fmaxf(x, 0.2x)
                e0 = fmaxf(e0, 0.2f * e0);
                e1 = fmaxf(e1, 0.2f * e1);
                e2 = fmaxf(e2, 0.2f * e2);
                e3 = fmaxf(e3, 0.2f * e3);
                float p0 = (av[r].x > 0) ? __expf(e0) : 0.0f;
                float p1 = (av[r].y > 0) ? __expf(e1) : 0.0f;
                float p2 = (av[r].z > 0) ? __expf(e2) : 0.0f;
                float p3 = (av[r].w > 0) ? __expf(e3) : 0.0f;
                *(float4*)&P_s[ii * 132 + lane * 4] = make_float4(p0, p1, p2, p3);
                float ps = (p0 + p1) + (p2 + p3);
#pragma unroll
                for (int o = 16; o >= 1; o >>= 1)
                    ps += __shfl_xor_sync(0xffffffffu, ps, o);
                if (lane == 0) den_s[ii] += ps;   // unique writer per row
            }
        }
        __syncthreads();

        // ---- phase 2: acc += P_tile @ Wh_tile  (4x8 microtile) ----
        for (int jj = 0; jj < 128; jj += 4) {
            float pa[4][4];
#pragma unroll
            for (int r = 0; r < 4; r++) {
                float4 v = *(const float4*)&P_s[(ty * 4 + r) * 132 + jj];
                pa[r][0] = v.x; pa[r][1] = v.y; pa[r][2] = v.z; pa[r][3] = v.w;
            }
#pragma unroll
            for (int q = 0; q < 4; q++) {
                float bf[8];
                *(float4*)&bf[0] = *(const float4*)&Wh_s[(jj + q) * 128 + tx * 8];
                *(float4*)&bf[4] = *(const float4*)&Wh_s[(jj + q) * 128 + tx * 8 + 4];
#pragma unroll
                for (int r = 0; r < 4; r++)
#pragma unroll
                    for (int c = 0; c < 8; c++)
                        acc[r][c] = fmaf(pa[r][q], bf[c], acc[r][c]);
            }
        }
        __syncthreads();
    }

    // ---- epilogue: divide by row sums, write out ----
#pragma unroll
    for (int r = 0; r < 4; r++) {
        int ii  = ty * 4 + r;
        int row = i0 + ii;
        float inv = 1.0f / den_s[ii];
        float4 v0 = make_float4(acc[r][0] * inv, acc[r][1] * inv,
                                acc[r][2] * inv, acc[r][3] * inv);
        float4 v1 = make_float4(acc[r][4] * inv, acc[r][5] * inv,
                                acc[r][6] * inv, acc[r][7] * inv);
        *(float4*)&out[(size_t)row * FOUT + tx * 8]     = v0;
        *(float4*)&out[(size_t)row * FOUT + tx * 8 + 4] = v1;
    }
}

// ---------------- launcher ----------------
extern "C" void kernel_launch(void* const* d_in, const int* in_sizes, int n_in,
                              void* d_out, int out_size)
{
    const float* h   = (const float*)d_in[0];
    const int*   adj = (const int*)  d_in[1];
    const float* W   = (const float*)d_in[2];
    const float* a   = (const float*)d_in[3];
    float* out = (float*)d_out;
    (void)in_sizes; (void)n_in; (void)out_size;

    cudaFuncSetAttribute(k2_attn, cudaFuncAttributeMaxDynamicSharedMemorySize,
                         K2_SMEM_BYTES);

    k1_gemm_s<<<NN / 64, 256>>>(h, W, a);
    k2_attn<<<NN / 64, 256, K2_SMEM_BYTES>>>(adj, out);
}

// round 3
// speedup vs baseline: 2.4581x; 2.4581x over previous
#include <cuda_runtime.h>
#include <cuda_bf16.h>
#include <cstdint>

#define NN   8192
#define FIN  256
#define FOUT 128

// ---------------- device scratch (no allocations allowed) ----------------
__device__ __align__(16) __nv_bfloat16 g_WhT_hi[FOUT * NN];   // 2 MB, [f][j]
__device__ __align__(16) __nv_bfloat16 g_WhT_lo[FOUT * NN];   // 2 MB
__device__ __align__(16) float g_num[2 * NN * FOUT];          // 8 MB split-j partials
__device__ float g_den[2 * NN];
__device__ float g_s1[NN];
__device__ float g_s2[NN];

// ---------------- warp-MMA helpers (sm_100 baseline: mma.sync + ldmatrix) ----------------
__device__ __forceinline__ uint32_t smem_u32(const void* p) {
    uint32_t a;
    asm("{ .reg .u64 t; cvta.to.shared.u64 t, %1; cvt.u32.u64 %0, t; }" : "=r"(a) : "l"(p));
    return a;
}
__device__ __forceinline__ void ldsm_x4(uint32_t* r, uint32_t addr) {
    asm volatile("ldmatrix.sync.aligned.m8n8.x4.shared.b16 {%0,%1,%2,%3}, [%4];"
                 : "=r"(r[0]), "=r"(r[1]), "=r"(r[2]), "=r"(r[3]) : "r"(addr));
}
__device__ __forceinline__ void ldsm_x2(uint32_t* r, uint32_t addr) {
    asm volatile("ldmatrix.sync.aligned.m8n8.x2.shared.b16 {%0,%1}, [%2];"
                 : "=r"(r[0]), "=r"(r[1]) : "r"(addr));
}
__device__ __forceinline__ void mma_bf16(float* d, const uint32_t* a, const uint32_t* b) {
    asm volatile(
        "mma.sync.aligned.m16n8k16.row.col.f32.bf16.bf16.f32 "
        "{%0,%1,%2,%3}, {%4,%5,%6,%7}, {%8,%9}, {%0,%1,%2,%3};"
        : "+f"(d[0]), "+f"(d[1]), "+f"(d[2]), "+f"(d[3])
        : "r"(a[0]), "r"(a[1]), "r"(a[2]), "r"(a[3]), "r"(b[0]), "r"(b[1]));
}

// ---------------- Kernel 1: Wh = h @ W -> WhT hi/lo bf16, s1, s2 ----------------
__global__ __launch_bounds__(256) void k1_gemm_s(
    const float* __restrict__ h, const float* __restrict__ W,
    const float* __restrict__ a)
{
    extern __shared__ float sm1[];
    float* h_t = sm1;                 // [64][36]
    float* W_t = sm1 + 64 * 36;       // [32][128]
    float* stage = sm1;               // [64][129] (reused after compute)

    const int t  = threadIdx.x;
    const int tx = t & 15;
    const int ty = t >> 4;
    const int row0 = blockIdx.x * 64;

    float acc[4][8];
#pragma unroll
    for (int r = 0; r < 4; r++)
#pragma unroll
        for (int c = 0; c < 8; c++) acc[r][c] = 0.0f;

    for (int k0 = 0; k0 < FIN; k0 += 32) {
        for (int l = t; l < 64 * 8; l += 256) {
            int r = l >> 3, c4 = l & 7;
            *(float4*)&h_t[r * 36 + c4 * 4] =
                *(const float4*)&h[(size_t)(row0 + r) * FIN + k0 + c4 * 4];
        }
        for (int l = t; l < 32 * 32; l += 256) {
            int r = l >> 5, c4 = l & 31;
            *(float4*)&W_t[r * 128 + c4 * 4] =
                *(const float4*)&W[(size_t)(k0 + r) * FOUT + c4 * 4];
        }
        __syncthreads();
#pragma unroll 8
        for (int k = 0; k < 32; k++) {
            float bf[8];
            *(float4*)&bf[0] = *(const float4*)&W_t[k * 128 + tx * 8];
            *(float4*)&bf[4] = *(const float4*)&W_t[k * 128 + tx * 8 + 4];
            float af[4];
#pragma unroll
            for (int r = 0; r < 4; r++) af[r] = h_t[(ty * 4 + r) * 36 + k];
#pragma unroll
            for (int r = 0; r < 4; r++)
#pragma unroll
                for (int c = 0; c < 8; c++)
                    acc[r][c] = fmaf(af[r], bf[c], acc[r][c]);
        }
        __syncthreads();
    }

    float a1f[8], a2f[8];
#pragma unroll
    for (int c = 0; c < 8; c++) {
        a1f[c] = a[tx * 8 + c];
        a2f[c] = a[FOUT + tx * 8 + c];
    }
#pragma unroll
    for (int r = 0; r < 4; r++) {
        int row = row0 + ty * 4 + r;
        float p1 = 0.f, p2 = 0.f;
#pragma unroll
        for (int c = 0; c < 8; c++) {
            p1 = fmaf(acc[r][c], a1f[c], p1);
            p2 = fmaf(acc[r][c], a2f[c], p2);
        }
#pragma unroll
        for (int o = 8; o >= 1; o >>= 1) {
            p1 += __shfl_xor_sync(0xffffffffu, p1, o);
            p2 += __shfl_xor_sync(0xffffffffu, p2, o);
        }
        if (tx == 0) { g_s1[row] = p1; g_s2[row] = p2; }
    }

    // stage acc -> smem, then write transposed bf16 hi/lo
#pragma unroll
    for (int r = 0; r < 4; r++) {
        int ii = ty * 4 + r;
#pragma unroll
        for (int c = 0; c < 8; c++) stage[ii * 129 + tx * 8 + c] = acc[r][c];
    }
    __syncthreads();

    {
        int c = t >> 1;            // output feature 0..127
        int half = t & 1;          // rows half*32 .. +32
        int rbase = half * 32;
#pragma unroll
        for (int k = 0; k < 32; k += 2) {
            float v0 = stage[(rbase + k) * 129 + c];
            float v1 = stage[(rbase + k + 1) * 129 + c];
            __nv_bfloat16 h0 = __float2bfloat16(v0);
            __nv_bfloat16 h1 = __float2bfloat16(v1);
            float l0f = v0 - __bfloat162float(h0);
            float l1f = v1 - __bfloat162float(h1);
            __nv_bfloat162 hp; hp.x = h0; hp.y = h1;
            __nv_bfloat162 lp; lp.x = __float2bfloat16(l0f); lp.y = __float2bfloat16(l1f);
            size_t idx = (size_t)c * NN + row0 + rbase + k;
            *(__nv_bfloat162*)&g_WhT_hi[idx] = hp;
            *(__nv_bfloat162*)&g_WhT_lo[idx] = lp;
        }
    }
}
#define K1_SMEM_BYTES (64 * 129 * 4)

// ---------------- Kernel 2: warp-MMA fused attention numerator ----------------
// 128 CTAs: blockIdx = tile*2 + half; i-tile 128 rows, 32 j-tiles of 128 per half.
// smem tiles: padded rows of 136 bf16 (272 B) -> ldmatrix conflict-free.
#define ROWB   272
#define TILE_B (128 * ROWB)          // 34816 bytes
#define A_HI_OFF   0
#define A_LO_OFF   (TILE_B)
#define B_HI_OFF   (2 * TILE_B)
#define B_LO_OFF   (3 * TILE_B)
#define S1_OFF     (4 * TILE_B)
#define DEN_OFF    (S1_OFF + 512)
#define K2_SMEM_BYTES (DEN_OFF + 512)

__global__ __launch_bounds__(256, 1) void k2_attn(const int* __restrict__ adj)
{
    extern __shared__ char base[];
    const uint32_t sb = smem_u32(base);

    float* s1_s  = (float*)(base + S1_OFF);
    float* den_s = (float*)(base + DEN_OFF);

    const int t    = threadIdx.x;
    const int lane = t & 31;
    const int w    = t >> 5;
    const int tile = blockIdx.x >> 1;
    const int half = blockIdx.x & 1;
    const int i0   = tile * 128;
    const int jbeg = half * 4096;

    // MMA sub-tile ownership: 4 m-splits x 2 n-splits
    const int mrow0 = (w & 3) * 32;
    const int ncol0 = (w >> 2) * 64;

    if (t < 128) { s1_s[t] = g_s1[i0 + t]; den_s[t] = 0.0f; }
    __syncthreads();

    float acc[64];                    // [mb(2)][nb(8)][4]
#pragma unroll
    for (int q = 0; q < 64; q++) acc[q] = 0.0f;

    // per-lane ldmatrix base offsets (bytes)
    const uint32_t a_off = sb + A_HI_OFF + (uint32_t)(mrow0 + (lane & 15)) * ROWB + (lane >> 4) * 16;
    const uint32_t b_off = sb + B_HI_OFF + (uint32_t)(ncol0 + (lane & 7)) * ROWB + ((lane >> 3) & 1) * 16;

    for (int it = 0; it < 32; it++) {
        const int j0 = jbeg + it * 128;

        // ---- stage B tiles (hi/lo Wh^T j-slab), padded layout ----
#pragma unroll
        for (int p = 0; p < 8; p++) {
            int l = t + p * 256;
            int r = l >> 4;                 // feature row 0..127
            int c = l & 15;                 // uint4 index (8 bf16)
            size_t gidx = (size_t)r * NN + j0 + c * 8;
            uint32_t soff = (uint32_t)r * ROWB + c * 16;
            *(uint4*)(base + B_HI_OFF + soff) = *(const uint4*)&g_WhT_hi[gidx];
            *(uint4*)(base + B_LO_OFF + soff) = *(const uint4*)&g_WhT_lo[gidx];
        }

        // ---- P tile: masked exp, fp32->bf16 hi/lo split, row sums ----
        {
            float4 s2v = *(const float4*)&g_s2[j0 + lane * 4];
#pragma unroll 4
            for (int r = 0; r < 16; r++) {
                int ii  = w * 16 + r;
                int4 av = *(const int4*)&adj[(size_t)(i0 + ii) * NN + j0 + lane * 4];
                float s1v = s1_s[ii];
                float e0 = s1v + s2v.x, e1 = s1v + s2v.y, e2 = s1v + s2v.z, e3 = s1v + s2v.w;
                e0 = fmaxf(e0, 0.2f * e0); e1 = fmaxf(e1, 0.2f * e1);
                e2 = fmaxf(e2, 0.2f * e2); e3 = fmaxf(e3, 0.2f * e3);
                float p0 = (av.x > 0) ? __expf(e0) : 0.0f;
                float p1 = (av.y > 0) ? __expf(e1) : 0.0f;
                float p2 = (av.z > 0) ? __expf(e2) : 0.0f;
                float p3 = (av.w > 0) ? __expf(e3) : 0.0f;

                __nv_bfloat162 h01 = __float22bfloat162_rn(make_float2(p0, p1));
                __nv_bfloat162 h23 = __float22bfloat162_rn(make_float2(p2, p3));
                float2 h01f = __bfloat1622float2(h01);
                float2 h23f = __bfloat1622float2(h23);
                __nv_bfloat162 l01 = __float22bfloat162_rn(make_float2(p0 - h01f.x, p1 - h01f.y));
                __nv_bfloat162 l23 = __float22bfloat162_rn(make_float2(p2 - h23f.x, p3 - h23f.y));

                uint32_t soff = (uint32_t)ii * ROWB + lane * 8;
                uint2 hv, lv;
                hv.x = *(uint32_t*)&h01; hv.y = *(uint32_t*)&h23;
                lv.x = *(uint32_t*)&l01; lv.y = *(uint32_t*)&l23;
                *(uint2*)(base + A_HI_OFF + soff) = hv;
                *(uint2*)(base + A_LO_OFF + soff) = lv;

                float ps = (p0 + p1) + (p2 + p3);
#pragma unroll
                for (int o = 16; o >= 1; o >>= 1)
                    ps += __shfl_xor_sync(0xffffffffu, ps, o);
                if (lane == 0) den_s[ii] += ps;
            }
        }
        __syncthreads();

        // ---- warp MMA: acc += P(hi/lo) @ WhT(hi/lo), 3 split terms ----
#pragma unroll
        for (int ks = 0; ks < 8; ks++) {
            uint32_t ao = a_off + ks * 32;
            uint32_t Ah0[4], Ah1[4], Al0[4], Al1[4];
            ldsm_x4(Ah0, ao);
            ldsm_x4(Ah1, ao + 16 * ROWB);
            ldsm_x4(Al0, ao + TILE_B);
            ldsm_x4(Al1, ao + TILE_B + 16 * ROWB);
#pragma unroll
            for (int nb = 0; nb < 8; nb++) {
                uint32_t bo = b_off + nb * 8 * ROWB + ks * 32;
                uint32_t Bh[2], Bl[2];
                ldsm_x2(Bh, bo);
                ldsm_x2(Bl, bo + TILE_B);
                float* d0 = &acc[(0 * 8 + nb) * 4];
                float* d1 = &acc[(1 * 8 + nb) * 4];
                mma_bf16(d0, Ah0, Bh);
                mma_bf16(d1, Ah1, Bh);
                mma_bf16(d0, Ah0, Bl);
                mma_bf16(d1, Ah1, Bl);
                mma_bf16(d0, Al0, Bh);
                mma_bf16(d1, Al1, Bh);
            }
        }
        __syncthreads();
    }

    // ---- epilogue: write numerator partial + denominator partial ----
#pragma unroll
    for (int mb = 0; mb < 2; mb++) {
#pragma unroll
        for (int nb = 0; nb < 8; nb++) {
            const float* d = &acc[(mb * 8 + nb) * 4];
            int row = i0 + mrow0 + mb * 16 + (lane >> 2);
            int col = ncol0 + nb * 8 + (lane & 3) * 2;
            size_t o0 = ((size_t)half * NN + row) * FOUT + col;
            *(float2*)&g_num[o0] = make_float2(d[0], d[1]);
            *(float2*)&g_num[o0 + 8 * FOUT] = make_float2(d[2], d[3]);
        }
    }
    if (t < 128) g_den[(size_t)half * NN + i0 + t] = den_s[t];
}

// ---------------- Kernel 3: combine split-j partials ----------------
__global__ __launch_bounds__(256) void k3_combine(float* __restrict__ out)
{
    int idx = blockIdx.x * 256 + threadIdx.x;       // float4 index
    int i = idx >> 5;                                // row
    float inv = 1.0f / (g_den[i] + g_den[NN + i]);
    float4 a = *(const float4*)&g_num[(size_t)idx * 4];
    float4 b = *(const float4*)&g_num[(size_t)NN * FOUT + (size_t)idx * 4];
    float4 o;
    o.x = (a.x + b.x) * inv; o.y = (a.y + b.y) * inv;
    o.z = (a.z + b.z) * inv; o.w = (a.w + b.w) * inv;
    *(float4*)&out[(size_t)idx * 4] = o;
}

// ---------------- launcher ----------------
extern "C" void kernel_launch(void* const* d_in, const int* in_sizes, int n_in,
                              void* d_out, int out_size)
{
    const float* h   = (const float*)d_in[0];
    const int*   adj = (const int*)  d_in[1];
    const float* W   = (const float*)d_in[2];
    const float* a   = (const float*)d_in[3];
    float* out = (float*)d_out;
    (void)in_sizes; (void)n_in; (void)out_size;

    cudaFuncSetAttribute(k2_attn, cudaFuncAttributeMaxDynamicSharedMemorySize, K2_SMEM_BYTES);

    k1_gemm_s<<<NN / 64, 256, K1_SMEM_BYTES>>>(h, W, a);
    k2_attn<<<NN / 64, 256, K2_SMEM_BYTES>>>(adj);
    k3_combine<<<NN * FOUT / 4 / 256, 256>>>(out);
}

// round 4
// speedup vs baseline: 3.8038x; 1.5474x over previous
#include <cuda_runtime.h>
#include <cuda_bf16.h>
#include <cstdint>

#define NN   8192
#define FIN  256
#define FOUT 128

// ---------------- device scratch (no allocations allowed) ----------------
__device__ __align__(16) __nv_bfloat16 g_WhT_hi[FOUT * NN];   // 2 MB, [f][j]
__device__ __align__(16) __nv_bfloat16 g_WhT_lo[FOUT * NN];   // 2 MB
__device__ __align__(16) float g_num[2 * NN * FOUT];          // 8 MB split-j partials
__device__ float g_den[2 * NN];
__device__ float g_s1[NN];
__device__ float g_s2[NN];

// ---------------- warp-MMA helpers ----------------
__device__ __forceinline__ uint32_t smem_u32(const void* p) {
    uint32_t a;
    asm("{ .reg .u64 t; cvta.to.shared.u64 t, %1; cvt.u32.u64 %0, t; }" : "=r"(a) : "l"(p));
    return a;
}
__device__ __forceinline__ void ldsm_x4(uint32_t* r, uint32_t addr) {
    asm volatile("ldmatrix.sync.aligned.m8n8.x4.shared.b16 {%0,%1,%2,%3}, [%4];"
                 : "=r"(r[0]), "=r"(r[1]), "=r"(r[2]), "=r"(r[3]) : "r"(addr));
}
__device__ __forceinline__ void mma_bf16(float* d, const uint32_t* a, const uint32_t* b) {
    asm volatile(
        "mma.sync.aligned.m16n8k16.row.col.f32.bf16.bf16.f32 "
        "{%0,%1,%2,%3}, {%4,%5,%6,%7}, {%8,%9}, {%0,%1,%2,%3};"
        : "+f"(d[0]), "+f"(d[1]), "+f"(d[2]), "+f"(d[3])
        : "r"(a[0]), "r"(a[1]), "r"(a[2]), "r"(a[3]), "r"(b[0]), "r"(b[1]));
}

// ---------------- Kernel 1: Wh = h @ W -> WhT hi/lo bf16, s1, s2 ----------------
// 256 CTAs x 32 rows (2x occupancy vs round 3).
__global__ __launch_bounds__(256) void k1_gemm_s(
    const float* __restrict__ h, const float* __restrict__ W,
    const float* __restrict__ a)
{
    extern __shared__ float sm1[];
    float* h_t = sm1;                 // [32][36]
    float* W_t = sm1 + 32 * 36;       // [32][128]
    float* stage = sm1;               // [32][129] (reused)

    const int t  = threadIdx.x;
    const int tx = t & 15;
    const int ty = t >> 4;            // 0..15, rows ty*2, ty*2+1
    const int row0 = blockIdx.x * 32;

    float acc[2][8];
#pragma unroll
    for (int r = 0; r < 2; r++)
#pragma unroll
        for (int c = 0; c < 8; c++) acc[r][c] = 0.0f;

    for (int k0 = 0; k0 < FIN; k0 += 32) {
        {
            int r = t >> 3, c4 = t & 7;   // 32 rows x 8 float4
            *(float4*)&h_t[r * 36 + c4 * 4] =
                *(const float4*)&h[(size_t)(row0 + r) * FIN + k0 + c4 * 4];
        }
#pragma unroll
        for (int p = 0; p < 4; p++) {
            int l = t + p * 256;
            int r = l >> 5, c4 = l & 31;
            *(float4*)&W_t[r * 128 + c4 * 4] =
                *(const float4*)&W[(size_t)(k0 + r) * FOUT + c4 * 4];
        }
        __syncthreads();
#pragma unroll 8
        for (int k = 0; k < 32; k++) {
            float bf[8];
            *(float4*)&bf[0] = *(const float4*)&W_t[k * 128 + tx * 8];
            *(float4*)&bf[4] = *(const float4*)&W_t[k * 128 + tx * 8 + 4];
            float af[2];
#pragma unroll
            for (int r = 0; r < 2; r++) af[r] = h_t[(ty * 2 + r) * 36 + k];
#pragma unroll
            for (int r = 0; r < 2; r++)
#pragma unroll
                for (int c = 0; c < 8; c++)
                    acc[r][c] = fmaf(af[r], bf[c], acc[r][c]);
        }
        __syncthreads();
    }

    float a1f[8], a2f[8];
#pragma unroll
    for (int c = 0; c < 8; c++) {
        a1f[c] = a[tx * 8 + c];
        a2f[c] = a[FOUT + tx * 8 + c];
    }
#pragma unroll
    for (int r = 0; r < 2; r++) {
        int row = row0 + ty * 2 + r;
        float p1 = 0.f, p2 = 0.f;
#pragma unroll
        for (int c = 0; c < 8; c++) {
            p1 = fmaf(acc[r][c], a1f[c], p1);
            p2 = fmaf(acc[r][c], a2f[c], p2);
        }
#pragma unroll
        for (int o = 8; o >= 1; o >>= 1) {
            p1 += __shfl_xor_sync(0xffffffffu, p1, o);
            p2 += __shfl_xor_sync(0xffffffffu, p2, o);
        }
        if (tx == 0) { g_s1[row] = p1; g_s2[row] = p2; }
    }

#pragma unroll
    for (int r = 0; r < 2; r++) {
        int ii = ty * 2 + r;
#pragma unroll
        for (int c = 0; c < 8; c++) stage[ii * 129 + tx * 8 + c] = acc[r][c];
    }
    __syncthreads();

    {
        int c = t >> 1;            // feature 0..127
        int rbase = (t & 1) * 16;  // half of 32 rows
#pragma unroll
        for (int k = 0; k < 16; k += 2) {
            float v0 = stage[(rbase + k) * 129 + c];
            float v1 = stage[(rbase + k + 1) * 129 + c];
            __nv_bfloat16 h0 = __float2bfloat16(v0);
            __nv_bfloat16 h1 = __float2bfloat16(v1);
            float l0f = v0 - __bfloat162float(h0);
            float l1f = v1 - __bfloat162float(h1);
            __nv_bfloat162 hp; hp.x = h0; hp.y = h1;
            __nv_bfloat162 lp; lp.x = __float2bfloat16(l0f); lp.y = __float2bfloat16(l1f);
            size_t idx = (size_t)c * NN + row0 + rbase + k;
            *(__nv_bfloat162*)&g_WhT_hi[idx] = hp;
            *(__nv_bfloat162*)&g_WhT_lo[idx] = lp;
        }
    }
}
#define K1_SMEM_BYTES ((32 * 36 + 32 * 128) * 4)

// ---------------- Kernel 2: pipelined warp-MMA attention numerator ----------------
// 128 CTAs (64 i-tiles x 2 j-halves). i-tile 128 rows; 64 j-tiles of 64.
// Per iteration: prefetch next tile (LDG->regs) | MMA current | exp/split/STS next | 1 sync.
#define ROWB   144                    // 64 bf16 + 8 pad = 144 B rows (ldmatrix conflict-free)
#define TILEB  (128 * ROWB)           // 18432 B per tile-half
#define BUFB   (4 * TILEB)            // A_hi, A_lo, B_hi, B_lo
#define S1_OFF (2 * BUFB)             // 147456
#define K2_SMEM_BYTES (S1_OFF + 512)

__global__ __launch_bounds__(256, 1) void k2_attn(const int* __restrict__ adj)
{
    extern __shared__ char base[];
    const uint32_t sb = smem_u32(base);
    float* s1_s = (float*)(base + S1_OFF);

    const int t    = threadIdx.x;
    const int lane = t & 31;
    const int w    = t >> 5;
    const int tile = blockIdx.x >> 1;
    const int half = blockIdx.x & 1;
    const int i0   = tile * 128;
    const int jbeg = half * 4096;

    const int mrow0 = (w & 3) * 32;    // MMA M ownership
    const int ncol0 = (w >> 2) * 64;   // MMA N ownership

    // exp-phase per-lane geometry: 8 iters, row = w*16 + r*2 + (lane>>4), 4 cols at (lane&15)*4
    const int xrow = w * 16 + (lane >> 4);
    const int xcol = (lane & 15) * 4;

    if (t < 128) s1_s[t] = g_s1[i0 + t];
    __syncthreads();

    float acc[64];
#pragma unroll
    for (int q = 0; q < 64; q++) acc[q] = 0.0f;
    float den_p[8];
#pragma unroll
    for (int r = 0; r < 8; r++) den_p[r] = 0.0f;

    // per-lane ldmatrix offsets (within a buffer)
    const uint32_t aLane = (uint32_t)(mrow0 + (lane & 15)) * ROWB + (lane >> 4) * 16;
    const uint32_t bLane = (uint32_t)(ncol0 + (lane & 7)) * ROWB + (lane >> 3) * 16;
    // staging geometry for B (WhT slab): 4 uint4 per thread per half
    const int bf0 = t >> 3;            // feature of first chunk (0..31), +32 per p
    const int bc  = (t & 7) * 16;      // byte column

    // ---------------- prologue: stage tile 0 into buffer 0 ----------------
    {
        const int j0n = jbeg;
#pragma unroll
        for (int p = 0; p < 4; p++) {
            int f = bf0 + p * 32;
            size_t g = (size_t)f * NN + j0n + (t & 7) * 8;
            *(uint4*)(base + 2 * TILEB + f * ROWB + bc) = *(const uint4*)&g_WhT_hi[g];
            *(uint4*)(base + 3 * TILEB + f * ROWB + bc) = *(const uint4*)&g_WhT_lo[g];
        }
        float4 s2v = *(const float4*)&g_s2[j0n + xcol];
#pragma unroll
        for (int r = 0; r < 8; r++) {
            int rl = xrow + r * 2;
            int4 av = *(const int4*)&adj[(size_t)(i0 + rl) * NN + j0n + xcol];
            float s1v = s1_s[rl];
            float e0 = s1v + s2v.x, e1 = s1v + s2v.y, e2 = s1v + s2v.z, e3 = s1v + s2v.w;
            e0 = fmaxf(e0, 0.2f * e0); e1 = fmaxf(e1, 0.2f * e1);
            e2 = fmaxf(e2, 0.2f * e2); e3 = fmaxf(e3, 0.2f * e3);
            float p0 = (av.x > 0) ? __expf(e0) : 0.0f;
            float p1 = (av.y > 0) ? __expf(e1) : 0.0f;
            float p2 = (av.z > 0) ? __expf(e2) : 0.0f;
            float p3 = (av.w > 0) ? __expf(e3) : 0.0f;
            __nv_bfloat162 h01 = __float22bfloat162_rn(make_float2(p0, p1));
            __nv_bfloat162 h23 = __float22bfloat162_rn(make_float2(p2, p3));
            float2 hf01 = __bfloat1622float2(h01);
            float2 hf23 = __bfloat1622float2(h23);
            __nv_bfloat162 l01 = __float22bfloat162_rn(make_float2(p0 - hf01.x, p1 - hf01.y));
            __nv_bfloat162 l23 = __float22bfloat162_rn(make_float2(p2 - hf23.x, p3 - hf23.y));
            uint2 hv, lv;
            hv.x = *(uint32_t*)&h01; hv.y = *(uint32_t*)&h23;
            lv.x = *(uint32_t*)&l01; lv.y = *(uint32_t*)&l23;
            uint32_t so = (uint32_t)rl * ROWB + (lane & 15) * 8;
            *(uint2*)(base + so) = hv;
            *(uint2*)(base + TILEB + so) = lv;
            den_p[r] += (p0 + p1) + (p2 + p3);
        }
    }
    __syncthreads();

    // ---------------- main loop ----------------
    for (int it = 0; it < 64; it++) {
        const uint32_t bufo = (uint32_t)(it & 1) * BUFB;
        const int has_next = (it < 63);

        // ---- issue next-tile global loads (latency hides under MMA) ----
        int4  adjv[8];
        uint4 whh[4], whl[4];
        float4 s2v;
        const int j0n = jbeg + (it + 1) * 64;
        if (has_next) {
#pragma unroll
            for (int r = 0; r < 8; r++) {
                int rl = xrow + r * 2;
                adjv[r] = *(const int4*)&adj[(size_t)(i0 + rl) * NN + j0n + xcol];
            }
#pragma unroll
            for (int p = 0; p < 4; p++) {
                int f = bf0 + p * 32;
                size_t g = (size_t)f * NN + j0n + (t & 7) * 8;
                whh[p] = *(const uint4*)&g_WhT_hi[g];
                whl[p] = *(const uint4*)&g_WhT_lo[g];
            }
            s2v = *(const float4*)&g_s2[j0n + xcol];
        }

        // ---- MMA on current buffers ----
        {
            const uint32_t ahi = sb + bufo + aLane;
            const uint32_t alo = ahi + TILEB;
            const uint32_t bhi = sb + bufo + 2 * TILEB + bLane;
            const uint32_t blo = bhi + TILEB;
#pragma unroll
            for (int kh = 0; kh < 2; kh++) {
                uint32_t Ah[2][2][4], Al[2][2][4];
#pragma unroll
                for (int mb = 0; mb < 2; mb++)
#pragma unroll
                    for (int k2 = 0; k2 < 2; k2++) {
                        uint32_t ao = mb * (16 * ROWB) + kh * 64 + k2 * 32;
                        ldsm_x4(Ah[mb][k2], ahi + ao);
                        ldsm_x4(Al[mb][k2], alo + ao);
                    }
#pragma unroll
                for (int nb = 0; nb < 8; nb++) {
                    uint32_t Bh[4], Bl[4];
                    uint32_t bo = nb * (8 * ROWB) + kh * 64;
                    ldsm_x4(Bh, bhi + bo);
                    ldsm_x4(Bl, blo + bo);
#pragma unroll
                    for (int k2 = 0; k2 < 2; k2++) {
#pragma unroll
                        for (int mb = 0; mb < 2; mb++) {
                            float* d = &acc[(mb * 8 + nb) * 4];
                            mma_bf16(d, Ah[mb][k2], &Bh[k2 * 2]);
                            mma_bf16(d, Ah[mb][k2], &Bl[k2 * 2]);
                            mma_bf16(d, Al[mb][k2], &Bh[k2 * 2]);
                        }
                    }
                }
            }
        }

        // ---- convert + store next tile into other buffer ----
        if (has_next) {
            const uint32_t nbuf = (uint32_t)((it + 1) & 1) * BUFB;
#pragma unroll
            for (int p = 0; p < 4; p++) {
                int f = bf0 + p * 32;
                *(uint4*)(base + nbuf + 2 * TILEB + f * ROWB + bc) = whh[p];
                *(uint4*)(base + nbuf + 3 * TILEB + f * ROWB + bc) = whl[p];
            }
#pragma unroll
            for (int r = 0; r < 8; r++) {
                int rl = xrow + r * 2;
                float s1v = s1_s[rl];
                float e0 = s1v + s2v.x, e1 = s1v + s2v.y, e2 = s1v + s2v.z, e3 = s1v + s2v.w;
                e0 = fmaxf(e0, 0.2f * e0); e1 = fmaxf(e1, 0.2f * e1);
                e2 = fmaxf(e2, 0.2f * e2); e3 = fmaxf(e3, 0.2f * e3);
                float p0 = (adjv[r].x > 0) ? __expf(e0) : 0.0f;
                float p1 = (adjv[r].y > 0) ? __expf(e1) : 0.0f;
                float p2 = (adjv[r].z > 0) ? __expf(e2) : 0.0f;
                float p3 = (adjv[r].w > 0) ? __expf(e3) : 0.0f;
                __nv_bfloat162 h01 = __float22bfloat162_rn(make_float2(p0, p1));
                __nv_bfloat162 h23 = __float22bfloat162_rn(make_float2(p2, p3));
                float2 hf01 = __bfloat1622float2(h01);
                float2 hf23 = __bfloat1622float2(h23);
                __nv_bfloat162 l01 = __float22bfloat162_rn(make_float2(p0 - hf01.x, p1 - hf01.y));
                __nv_bfloat162 l23 = __float22bfloat162_rn(make_float2(p2 - hf23.x, p3 - hf23.y));
                uint2 hv, lv;
                hv.x = *(uint32_t*)&h01; hv.y = *(uint32_t*)&h23;
                lv.x = *(uint32_t*)&l01; lv.y = *(uint32_t*)&l23;
                uint32_t so = nbuf + (uint32_t)rl * ROWB + (lane & 15) * 8;
                *(uint2*)(base + so) = hv;
                *(uint2*)(base + TILEB + so) = lv;
                den_p[r] += (p0 + p1) + (p2 + p3);
            }
        }
        __syncthreads();
    }

    // ---- den: single reduction at the end ----
#pragma unroll
    for (int r = 0; r < 8; r++) {
#pragma unroll
        for (int o = 8; o >= 1; o >>= 1)
            den_p[r] += __shfl_xor_sync(0xffffffffu, den_p[r], o);
    }
    if ((lane & 15) == 0) {
#pragma unroll
        for (int r = 0; r < 8; r++)
            g_den[(size_t)half * NN + i0 + xrow + r * 2] = den_p[r];
    }

    // ---- write numerator partial ----
#pragma unroll
    for (int mb = 0; mb < 2; mb++) {
#pragma unroll
        for (int nb = 0; nb < 8; nb++) {
            const float* d = &acc[(mb * 8 + nb) * 4];
            int row = i0 + mrow0 + mb * 16 + (lane >> 2);
            int col = ncol0 + nb * 8 + (lane & 3) * 2;
            size_t o0 = ((size_t)half * NN + row) * FOUT + col;
            *(float2*)&g_num[o0] = make_float2(d[0], d[1]);
            *(float2*)&g_num[o0 + 8 * FOUT] = make_float2(d[2], d[3]);
        }
    }
}

// ---------------- Kernel 3: combine split-j partials ----------------
__global__ __launch_bounds__(256) void k3_combine(float* __restrict__ out)
{
    int idx = blockIdx.x * 256 + threadIdx.x;       // float4 index
    int i = idx >> 5;                                // row
    float inv = 1.0f / (g_den[i] + g_den[NN + i]);
    float4 a = *(const float4*)&g_num[(size_t)idx * 4];
    float4 b = *(const float4*)&g_num[(size_t)NN * FOUT + (size_t)idx * 4];
    float4 o;
    o.x = (a.x + b.x) * inv; o.y = (a.y + b.y) * inv;
    o.z = (a.z + b.z) * inv; o.w = (a.w + b.w) * inv;
    *(float4*)&out[(size_t)idx * 4] = o;
}

// ---------------- launcher ----------------
extern "C" void kernel_launch(void* const* d_in, const int* in_sizes, int n_in,
                              void* d_out, int out_size)
{
    const float* h   = (const float*)d_in[0];
    const int*   adj = (const int*)  d_in[1];
    const float* W   = (const float*)d_in[2];
    const float* a   = (const float*)d_in[3];
    float* out = (float*)d_out;
    (void)in_sizes; (void)n_in; (void)out_size;

    cudaFuncSetAttribute(k2_attn, cudaFuncAttributeMaxDynamicSharedMemorySize, K2_SMEM_BYTES);

    k1_gemm_s<<<NN / 32, 256, K1_SMEM_BYTES>>>(h, W, a);
    k2_attn<<<NN / 64, 256, K2_SMEM_BYTES>>>(adj);
    k3_combine<<<NN * FOUT / 4 / 256, 256>>>(out);
}

// round 5
// speedup vs baseline: 4.6066x; 1.2110x over previous
#include <cuda_runtime.h>
#include <cuda_fp16.h>
#include <cstdint>

#define NN   8192
#define FIN  256
#define FOUT 128

// ---------------- device scratch ----------------
__device__ __align__(16) __half g_WhT_hi[FOUT * NN];   // 2 MB, [f][j]
__device__ __align__(16) __half g_WhT_lo[FOUT * NN];   // 2 MB
__device__ __align__(16) float g_num[2 * NN * FOUT];   // split-j partials
__device__ float g_den[2 * NN];
__device__ float g_s1[NN];
__device__ float g_s2[NN];

// ---------------- helpers ----------------
__device__ __forceinline__ uint32_t smem_u32(const void* p) {
    uint32_t a;
    asm("{ .reg .u64 t; cvta.to.shared.u64 t, %1; cvt.u32.u64 %0, t; }" : "=r"(a) : "l"(p));
    return a;
}
__device__ __forceinline__ void ldsm_x4(uint32_t* r, uint32_t addr) {
    asm volatile("ldmatrix.sync.aligned.m8n8.x4.shared.b16 {%0,%1,%2,%3}, [%4];"
                 : "=r"(r[0]), "=r"(r[1]), "=r"(r[2]), "=r"(r[3]) : "r"(addr));
}
__device__ __forceinline__ void mma_f16(float* d, const uint32_t* a, uint32_t b0, uint32_t b1) {
    asm volatile(
        "mma.sync.aligned.m16n8k16.row.col.f32.f16.f16.f32 "
        "{%0,%1,%2,%3}, {%4,%5,%6,%7}, {%8,%9}, {%0,%1,%2,%3};"
        : "+f"(d[0]), "+f"(d[1]), "+f"(d[2]), "+f"(d[3])
        : "r"(a[0]), "r"(a[1]), "r"(a[2]), "r"(a[3]), "r"(b0), "r"(b1));
}
__device__ __forceinline__ void cp_async16(uint32_t dst, const void* src) {
    asm volatile("cp.async.cg.shared.global [%0], [%1], 16;" :: "r"(dst), "l"(src));
}
#define CP_COMMIT() asm volatile("cp.async.commit_group;" ::: "memory")
#define CP_WAIT0()  asm volatile("cp.async.wait_group 0;" ::: "memory")

// ---------------- Kernel 1: Wh = h @ W (fp16 3-term tensor), s1, s2, WhT hi/lo ----------------
// 128 CTAs x 256 thr; 64 rows each. smem: Ah|Al (64x528 B) Bh|Bl (128x528 B)
#define R1    528                     // 256 fp16 = 512 B + 16 pad
#define AH1   0
#define AL1   (64 * R1)               // 33792
#define BH1   (2 * 64 * R1)           // 67584
#define BL1   (BH1 + 128 * R1)        // 135168
#define K1_SMEM_BYTES (BL1 + 128 * R1)  // 202752
#define ASTG_OFF  0                   // fp32 stage [64][132], reuses A region
#define AVEC_OFF  (64 * 132 * 4)      // a vector copy (256 floats)

__global__ __launch_bounds__(256, 1) void k1_gemm_s(
    const float* __restrict__ h, const float* __restrict__ W,
    const float* __restrict__ a)
{
    extern __shared__ char base[];
    const uint32_t sb = smem_u32(base);
    const int t    = threadIdx.x;
    const int lane = t & 31;
    const int w    = t >> 5;
    const int row0 = blockIdx.x * 64;

    // ---- stage h tile (64x256) -> fp16 hi/lo split ----
#pragma unroll
    for (int p = 0; p < 16; p++) {
        int id = t + p * 256;             // 0..4095 float4s
        int r = id >> 6, c4 = id & 63;
        float4 v = *(const float4*)&h[(size_t)(row0 + r) * FIN + c4 * 4];
        __half hi0 = __float2half_rn(v.x), hi1 = __float2half_rn(v.y);
        __half hi2 = __float2half_rn(v.z), hi3 = __float2half_rn(v.w);
        __half lo0 = __float2half_rn(v.x - __half2float(hi0));
        __half lo1 = __float2half_rn(v.y - __half2float(hi1));
        __half lo2 = __float2half_rn(v.z - __half2float(hi2));
        __half lo3 = __float2half_rn(v.w - __half2float(hi3));
        __half2 hp0; hp0.x = hi0; hp0.y = hi1;
        __half2 hp1; hp1.x = hi2; hp1.y = hi3;
        __half2 lp0; lp0.x = lo0; lp0.y = lo1;
        __half2 lp1; lp1.x = lo2; lp1.y = lo3;
        uint2 hv, lv;
        hv.x = *(uint32_t*)&hp0; hv.y = *(uint32_t*)&hp1;
        lv.x = *(uint32_t*)&lp0; lv.y = *(uint32_t*)&lp1;
        uint32_t off = (uint32_t)r * R1 + c4 * 8;
        *(uint2*)(base + AH1 + off) = hv;
        *(uint2*)(base + AL1 + off) = lv;
    }
    // ---- stage W transposed (WT[f][k]) fp16 hi/lo ----
#pragma unroll
    for (int p = 0; p < 32; p++) {
        int id = t + p * 256;             // 0..8191 float4s
        int r = id >> 5, c4 = id & 31;    // r = k, c4*4 = f
        float4 v = *(const float4*)&W[(size_t)r * FOUT + c4 * 4];
        float vv[4] = {v.x, v.y, v.z, v.w};
#pragma unroll
        for (int e = 0; e < 4; e++) {
            int f = c4 * 4 + e;
            __half hi = __float2half_rn(vv[e]);
            __half lo = __float2half_rn(vv[e] - __half2float(hi));
            *(__half*)(base + BH1 + (uint32_t)f * R1 + r * 2) = hi;
            *(__half*)(base + BL1 + (uint32_t)f * R1 + r * 2) = lo;
        }
    }
    __syncthreads();

    // ---- MMA: 3-term fp16 split over K=256 ----
    const int mrow0 = (w & 1) * 32;
    const int ncol0 = (w >> 1) * 32;
    float acc[32];
#pragma unroll
    for (int q = 0; q < 32; q++) acc[q] = 0.0f;

    const uint32_t aH = sb + AH1 + (uint32_t)(mrow0 + (lane & 15)) * R1 + (lane >> 4) * 16;
    const uint32_t aL = aH + (AL1 - AH1);
    const uint32_t bH = sb + BH1 + (uint32_t)(ncol0 + (lane & 15)) * R1 + (lane >> 4) * 16;
    const uint32_t bL = bH + (BL1 - BH1);

#pragma unroll
    for (int ks = 0; ks < 16; ks++) {
        uint32_t Ah[2][4], Al[2][4], Bh[2][4], Bl[2][4];
#pragma unroll
        for (int mb = 0; mb < 2; mb++) {
            ldsm_x4(Ah[mb], aH + mb * (16 * R1) + ks * 32);
            ldsm_x4(Al[mb], aL + mb * (16 * R1) + ks * 32);
        }
#pragma unroll
        for (int nb = 0; nb < 2; nb++) {
            ldsm_x4(Bh[nb], bH + nb * (16 * R1) + ks * 32);
            ldsm_x4(Bl[nb], bL + nb * (16 * R1) + ks * 32);
        }
#pragma unroll
        for (int mb = 0; mb < 2; mb++)
#pragma unroll
            for (int nb = 0; nb < 2; nb++)
#pragma unroll
                for (int s = 0; s < 2; s++) {
                    float* d = &acc[(mb * 4 + nb * 2 + s) * 4];
                    mma_f16(d, Ah[mb], Bh[nb][s], Bh[nb][s + 2]);
                    mma_f16(d, Ah[mb], Bl[nb][s], Bl[nb][s + 2]);
                    mma_f16(d, Al[mb], Bh[nb][s], Bh[nb][s + 2]);
                }
    }
    __syncthreads();

    // ---- stage Wh fp32 tile for transpose + s1/s2 ----
    float* stage = (float*)(base + ASTG_OFF);
    float* a_s   = (float*)(base + AVEC_OFF);
#pragma unroll
    for (int mb = 0; mb < 2; mb++)
#pragma unroll
        for (int nb8 = 0; nb8 < 4; nb8++) {
            const float* d = &acc[(mb * 4 + nb8) * 4];
            int row = mrow0 + mb * 16 + (lane >> 2);
            int col = ncol0 + nb8 * 8 + (lane & 3) * 2;
            stage[row * 132 + col]     = d[0];
            stage[row * 132 + col + 1] = d[1];
            stage[(row + 8) * 132 + col]     = d[2];
            stage[(row + 8) * 132 + col + 1] = d[3];
        }
    a_s[t] = a[t];
    __syncthreads();

    // s1/s2
    if (t < 64) {
        float p1 = 0.f, p2 = 0.f;
#pragma unroll 8
        for (int c = 0; c < 128; c++) {
            float v = stage[t * 132 + c];
            p1 = fmaf(v, a_s[c], p1);
            p2 = fmaf(v, a_s[128 + c], p2);
        }
        g_s1[row0 + t] = p1;
        g_s2[row0 + t] = p2;
    }
    // WhT fp16 hi/lo writes
    {
        int c = t >> 1;
        int rh = (t & 1) * 32;
#pragma unroll
        for (int r = 0; r < 32; r += 2) {
            float v0 = stage[(rh + r) * 132 + c];
            float v1 = stage[(rh + r + 1) * 132 + c];
            __half h0 = __float2half_rn(v0), h1 = __float2half_rn(v1);
            __half2 hp; hp.x = h0; hp.y = h1;
            __half2 lp;
            lp.x = __float2half_rn(v0 - __half2float(h0));
            lp.y = __float2half_rn(v1 - __half2float(h1));
            size_t idx = (size_t)c * NN + row0 + rh + r;
            *(__half2*)&g_WhT_hi[idx] = hp;
            *(__half2*)&g_WhT_lo[idx] = lp;
        }
    }
}

// ---------------- Kernel 2: pipelined fp16 warp-MMA attention ----------------
// 128 CTAs (64 i-tiles x 2 j-halves); i-tile 128 rows; 64 j-tiles of 64.
// A = P fp16 single; B = WhT fp16 hi+lo (2 mma per k16).
#define ROWB  144
#define TILEA (128 * ROWB)            // 18432
#define BHOF  TILEA
#define BLOF  (2 * TILEA)
#define BUFB  (3 * TILEA)             // 55296
#define S1_OFF (2 * BUFB)             // 110592
#define K2_SMEM_BYTES (S1_OFF + 512)

__global__ __launch_bounds__(256, 1) void k2_attn(const int* __restrict__ adj)
{
    extern __shared__ char base[];
    const uint32_t sb = smem_u32(base);
    float* s1_s = (float*)(base + S1_OFF);

    const int t    = threadIdx.x;
    const int lane = t & 31;
    const int w    = t >> 5;
    const int tile = blockIdx.x >> 1;
    const int half = blockIdx.x & 1;
    const int i0   = tile * 128;
    const int jbeg = half * 4096;

    const int mrow0 = (w & 1) * 64;   // 2 m-splits
    const int ncol0 = (w >> 1) * 32;  // 4 n-splits

    const int xrow = w * 16 + (lane >> 4);
    const int xcol = (lane & 15) * 4;
    const int bf   = (t + 0) >> 3;    // cp.async: feature row per chunk-id base
    const int bcid = t & 7;           // 16B chunk within row

    if (t < 128) s1_s[t] = g_s1[i0 + t];
    __syncthreads();

    float acc[64];
#pragma unroll
    for (int q = 0; q < 64; q++) acc[q] = 0.0f;
    float den_p[8];
#pragma unroll
    for (int r = 0; r < 8; r++) den_p[r] = 0.0f;

    const uint32_t aLane = (uint32_t)(mrow0 + (lane & 15)) * ROWB + (lane >> 4) * 16;
    const uint32_t bLane = (uint32_t)(ncol0 + (lane & 15)) * ROWB + (lane >> 4) * 16;

    // ---------------- prologue: tile 0 ----------------
    {
        const int j0n = jbeg;
#pragma unroll
        for (int p = 0; p < 4; p++) {
            int f = bf + p * 32;
            size_t g = (size_t)f * NN + j0n + bcid * 8;
            uint32_t d = sb + f * ROWB + bcid * 16;
            cp_async16(d + BHOF, &g_WhT_hi[g]);
            cp_async16(d + BLOF, &g_WhT_lo[g]);
        }
        CP_COMMIT();
        float4 s2v = *(const float4*)&g_s2[j0n + xcol];
#pragma unroll
        for (int r = 0; r < 8; r++) {
            int rl = xrow + r * 2;
            int4 av = *(const int4*)&adj[(size_t)(i0 + rl) * NN + j0n + xcol];
            float s1v = s1_s[rl];
            float e0 = s1v + s2v.x, e1 = s1v + s2v.y, e2 = s1v + s2v.z, e3 = s1v + s2v.w;
            e0 = fmaxf(e0, 0.2f * e0); e1 = fmaxf(e1, 0.2f * e1);
            e2 = fmaxf(e2, 0.2f * e2); e3 = fmaxf(e3, 0.2f * e3);
            float p0 = (av.x > 0) ? __expf(e0) : 0.0f;
            float p1 = (av.y > 0) ? __expf(e1) : 0.0f;
            float p2 = (av.z > 0) ? __expf(e2) : 0.0f;
            float p3 = (av.w > 0) ? __expf(e3) : 0.0f;
            __half2 q01 = __floats2half2_rn(p0, p1);
            __half2 q23 = __floats2half2_rn(p2, p3);
            uint2 hv; hv.x = *(uint32_t*)&q01; hv.y = *(uint32_t*)&q23;
            *(uint2*)(base + (uint32_t)rl * ROWB + (lane & 15) * 8) = hv;
            den_p[r] += (p0 + p1) + (p2 + p3);
        }
        CP_WAIT0();
    }
    __syncthreads();

    // ---------------- main loop ----------------
    for (int it = 0; it < 64; it++) {
        const uint32_t bufo = (uint32_t)(it & 1) * BUFB;
        const uint32_t nbuf = (uint32_t)((it + 1) & 1) * BUFB;
        const int has_next = (it < 63);
        const int j0n = jbeg + (it + 1) * 64;

        int4  adjv[8];
        float4 s2v;
        if (has_next) {
#pragma unroll
            for (int p = 0; p < 4; p++) {
                int f = bf + p * 32;
                size_t g = (size_t)f * NN + j0n + bcid * 8;
                uint32_t d = sb + nbuf + f * ROWB + bcid * 16;
                cp_async16(d + BHOF, &g_WhT_hi[g]);
                cp_async16(d + BLOF, &g_WhT_lo[g]);
            }
            CP_COMMIT();
#pragma unroll
            for (int r = 0; r < 8; r++) {
                int rl = xrow + r * 2;
                adjv[r] = *(const int4*)&adj[(size_t)(i0 + rl) * NN + j0n + xcol];
            }
            s2v = *(const float4*)&g_s2[j0n + xcol];
        }

        // ---- MMA on current buffers ----
        {
            const uint32_t aA = sb + bufo + aLane;
            const uint32_t aBH = sb + bufo + BHOF + bLane;
            const uint32_t aBL = sb + bufo + BLOF + bLane;
#pragma unroll
            for (int ks = 0; ks < 4; ks++) {
                uint32_t Ah[4][4];
#pragma unroll
                for (int mb = 0; mb < 4; mb++)
                    ldsm_x4(Ah[mb], aA + mb * (16 * ROWB) + ks * 32);
                uint32_t Bh[2][4], Bl[2][4];
#pragma unroll
                for (int nb = 0; nb < 2; nb++) {
                    ldsm_x4(Bh[nb], aBH + nb * (16 * ROWB) + ks * 32);
                    ldsm_x4(Bl[nb], aBL + nb * (16 * ROWB) + ks * 32);
                }
#pragma unroll
                for (int mb = 0; mb < 4; mb++)
#pragma unroll
                    for (int nb = 0; nb < 2; nb++)
#pragma unroll
                        for (int s = 0; s < 2; s++) {
                            float* d = &acc[(mb * 4 + nb * 2 + s) * 4];
                            mma_f16(d, Ah[mb], Bh[nb][s], Bh[nb][s + 2]);
                            mma_f16(d, Ah[mb], Bl[nb][s], Bl[nb][s + 2]);
                        }
            }
        }

        // ---- exp/convert next tile -> A[nbuf] ----
        if (has_next) {
#pragma unroll
            for (int r = 0; r < 8; r++) {
                int rl = xrow + r * 2;
                float s1v = s1_s[rl];
                float e0 = s1v + s2v.x, e1 = s1v + s2v.y, e2 = s1v + s2v.z, e3 = s1v + s2v.w;
                e0 = fmaxf(e0, 0.2f * e0); e1 = fmaxf(e1, 0.2f * e1);
                e2 = fmaxf(e2, 0.2f * e2); e3 = fmaxf(e3, 0.2f * e3);
                float p0 = (adjv[r].x > 0) ? __expf(e0) : 0.0f;
                float p1 = (adjv[r].y > 0) ? __expf(e1) : 0.0f;
                float p2 = (adjv[r].z > 0) ? __expf(e2) : 0.0f;
                float p3 = (adjv[r].w > 0) ? __expf(e3) : 0.0f;
                __half2 q01 = __floats2half2_rn(p0, p1);
                __half2 q23 = __floats2half2_rn(p2, p3);
                uint2 hv; hv.x = *(uint32_t*)&q01; hv.y = *(uint32_t*)&q23;
                *(uint2*)(base + nbuf + (uint32_t)rl * ROWB + (lane & 15) * 8) = hv;
                den_p[r] += (p0 + p1) + (p2 + p3);
            }
        }
        CP_WAIT0();
        __syncthreads();
    }

    // ---- den reduction (rows shared by the 16 lanes of a half) ----
#pragma unroll
    for (int r = 0; r < 8; r++) {
#pragma unroll
        for (int o = 8; o >= 1; o >>= 1)
            den_p[r] += __shfl_xor_sync(0xffffffffu, den_p[r], o);
    }
    if ((lane & 15) == 0) {
#pragma unroll
        for (int r = 0; r < 8; r++)
            g_den[(size_t)half * NN + i0 + xrow + r * 2] = den_p[r];
    }

    // ---- write numerator partial ----
#pragma unroll
    for (int mb = 0; mb < 4; mb++)
#pragma unroll
        for (int nb8 = 0; nb8 < 4; nb8++) {
            const float* d = &acc[(mb * 4 + nb8) * 4];
            int row = i0 + mrow0 + mb * 16 + (lane >> 2);
            int col = ncol0 + nb8 * 8 + (lane & 3) * 2;
            size_t o0 = ((size_t)half * NN + row) * FOUT + col;
            *(float2*)&g_num[o0] = make_float2(d[0], d[1]);
            *(float2*)&g_num[o0 + 8 * FOUT] = make_float2(d[2], d[3]);
        }
}

// ---------------- Kernel 3: combine split-j partials ----------------
__global__ __launch_bounds__(256) void k3_combine(float* __restrict__ out)
{
    int idx = blockIdx.x * 256 + threadIdx.x;
    int i = idx >> 5;
    float inv = 1.0f / (g_den[i] + g_den[NN + i]);
    float4 a = *(const float4*)&g_num[(size_t)idx * 4];
    float4 b = *(const float4*)&g_num[(size_t)NN * FOUT + (size_t)idx * 4];
    float4 o;
    o.x = (a.x + b.x) * inv; o.y = (a.y + b.y) * inv;
    o.z = (a.z + b.z) * inv; o.w = (a.w + b.w) * inv;
    *(float4*)&out[(size_t)idx * 4] = o;
}

// ---------------- launcher ----------------
extern "C" void kernel_launch(void* const* d_in, const int* in_sizes, int n_in,
                              void* d_out, int out_size)
{
    const float* h   = (const float*)d_in[0];
    const int*   adj = (const int*)  d_in[1];
    const float* W   = (const float*)d_in[2];
    const float* a   = (const float*)d_in[3];
    float* out = (float*)d_out;
    (void)in_sizes; (void)n_in; (void)out_size;

    cudaFuncSetAttribute(k1_gemm_s, cudaFuncAttributeMaxDynamicSharedMemorySize, K1_SMEM_BYTES);
    cudaFuncSetAttribute(k2_attn,  cudaFuncAttributeMaxDynamicSharedMemorySize, K2_SMEM_BYTES);

    k1_gemm_s<<<NN / 64, 256, K1_SMEM_BYTES>>>(h, W, a);
    k2_attn<<<NN / 64, 256, K2_SMEM_BYTES>>>(adj);
    k3_combine<<<NN * FOUT / 4 / 256, 256>>>(out);
}